// round 3
// baseline (speedup 1.0000x reference)
#include <cuda_runtime.h>

#define TOT 8192
#define BN 16
#define C 64
#define K 20
#define CN 512
#define NW (BN*CN)
#define STEPS 8
#define BN_EPS 1e-5f

// ---- device scratch (static; no allocations) ----
__device__ float  g_xT[(size_t)BN*TOT*C];        // x transposed (b,node,ch) 32MB
__device__ float2 g_ssq[(size_t)BN*TOT];         // per-node (dot(x,w_lo), |x|^2)
__device__ float  g_curves[(size_t)STEPS*NW*C];  // [step][w][ch] 16MB
__device__ float  g_curf[(size_t)NW*C];
__device__ float  g_pref[(size_t)NW*C];
__device__ int    g_curidx[NW];
__device__ float  g_S[BN*2*CN];                  // softmax exchange

// ---------------- transpose x (b,c,tot) -> xT (b,tot,c), float4 both sides ----
__global__ __launch_bounds__(256)
void transpose_x_kernel(const float* __restrict__ x) {
    __shared__ float tile[32][33];
    int b = blockIdx.z;
    int node0 = blockIdx.x * 32;
    int ch0 = blockIdx.y * 32;
    int tx = threadIdx.x;   // 0..7
    int ty = threadIdx.y;   // 0..31
    const float4* src = (const float4*)(x + (size_t)b * C * TOT
                                          + (size_t)(ch0 + ty) * TOT + node0);
    float4 v = __ldg(&src[tx]);
    tile[ty][tx*4+0] = v.x; tile[ty][tx*4+1] = v.y;
    tile[ty][tx*4+2] = v.z; tile[ty][tx*4+3] = v.w;
    __syncthreads();
    int r = ty, c4 = tx * 4;
    float4 o = make_float4(tile[c4][r], tile[c4+1][r], tile[c4+2][r], tile[c4+3][r]);
    float4* dst = (float4*)(g_xT + (size_t)b * TOT * C + (size_t)(node0 + r) * C + ch0);
    dst[tx] = o;
}

// ---------------- per-node s = dot(x, w_lo), sq = |x|^2 ----------------
__global__ __launch_bounds__(256)
void ssq_kernel(const float* __restrict__ agent_w) {
    int t = blockIdx.x * 256 + threadIdx.x;        // global node 0..BN*TOT-1
    const float4* row = (const float4*)(g_xT + (size_t)t * C);
    const float4* wv = (const float4*)agent_w;
    float s = 0.f, q = 0.f;
    #pragma unroll
    for (int i = 0; i < 16; i++) {
        float4 v = row[i];
        float4 wl = __ldg(&wv[i]);
        s += v.x*wl.x + v.y*wl.y + v.z*wl.z + v.w*wl.w;
        q += v.x*v.x + v.y*v.y + v.z*v.z + v.w*v.w;
    }
    g_ssq[t] = make_float2(s, q);
}

__device__ __forceinline__ float dot8(const float4& a0, const float4& a1,
                                      const float4& b0, const float4& b1) {
    return a0.x*b0.x + a0.y*b0.y + a0.z*b0.z + a0.w*b0.w
         + a1.x*b1.x + a1.y*b1.y + a1.z*b1.z + a1.w*b1.w;
}

// ---------------- one walk step; 8 lanes per walker ----------------
template<bool FIRST>
__global__ __launch_bounds__(256, 3)
void walk_step_kernel(
    const int* __restrict__ adj, const int* __restrict__ cur0,
    const float* __restrict__ agent_w,
    const float* __restrict__ agent_gamma, const float* __restrict__ agent_beta,
    const float* __restrict__ agent_mean,  const float* __restrict__ agent_var,
    const float* __restrict__ mom_w,
    const float* __restrict__ mom_gamma, const float* __restrict__ mom_beta,
    const float* __restrict__ mom_mean,  const float* __restrict__ mom_var,
    int step)
{
    int tid = blockIdx.x * 256 + threadIdx.x;
    int w = tid >> 3;
    int sub = threadIdx.x & 7;
    int b = w >> 9;
    int n = w & 511;

    const float4* wv = (const float4*)agent_w;
    float4 whA = __ldg(&wv[16 + sub]), whB = __ldg(&wv[24 + sub]);  // agent_w[64:128]

    float inv_a  = __ldg(agent_gamma) / sqrtf(__ldg(agent_var) + BN_EPS);
    float mean_a = __ldg(agent_mean);
    float beta_a = __ldg(agent_beta);

    const float* xTb = g_xT + (size_t)b * TOT * C;
    const float2* ssqb = g_ssq + (size_t)b * TOT;

    float4 cfA, cfB, pfA, pfB, cvA, cvB;
    int cidx;
    float tpp, n1, cvcf = 0.f, cf2 = 0.f;

    if (FIRST) {
        cidx = __ldg(&cur0[w]);
        const float4* pv = (const float4*)(xTb + (size_t)cidx * C);
        pfA = __ldg(&pv[sub]); pfB = __ldg(&pv[8 + sub]);
        tpp = dot8(pfA, pfB, whA, whB);
        #pragma unroll
        for (int off = 1; off <= 4; off <<= 1)
            tpp += __shfl_xor_sync(0xffffffffu, tpp, off);
        n1 = 0.f;
        cfA = make_float4(0.f,0.f,0.f,0.f); cfB = cfA; cvA = cfA; cvB = cfA;
    } else {
        cidx = g_curidx[w];
        const float4* cf = (const float4*)(g_curf + (size_t)w * C);
        cfA = cf[sub]; cfB = cf[8 + sub];
        const float4* pf = (const float4*)(g_pref + (size_t)w * C);
        pfA = pf[sub]; pfB = pf[8 + sub];
        float a0 = g_S[b * 1024 + 2 * n];
        float a1 = g_S[b * 1024 + 2 * n + 1];
        pfA.x = cfA.x*a0 + pfA.x*a1;  pfA.y = cfA.y*a0 + pfA.y*a1;
        pfA.z = cfA.z*a0 + pfA.z*a1;  pfA.w = cfA.w*a0 + pfA.w*a1;
        pfB.x = cfB.x*a0 + pfB.x*a1;  pfB.y = cfB.y*a0 + pfB.y*a1;
        pfB.z = cfB.z*a0 + pfB.z*a1;  pfB.w = cfB.w*a0 + pfB.w*a1;
        cvA.x = cfA.x - pfA.x; cvA.y = cfA.y - pfA.y;
        cvA.z = cfA.z - pfA.z; cvA.w = cfA.w - pfA.w;
        cvB.x = cfB.x - pfB.x; cvB.y = cfB.y - pfB.y;
        cvB.z = cfB.z - pfB.z; cvB.w = cfB.w - pfB.w;

        float tppp = dot8(pfA, pfB, whA, whB);
        float n1pp = dot8(cvA, cvB, cvA, cvB);
        float cvcfp = dot8(cvA, cvB, cfA, cfB);
        float cf2p  = dot8(cfA, cfB, cfA, cfB);
        #pragma unroll
        for (int off = 1; off <= 4; off <<= 1) {
            tppp  += __shfl_xor_sync(0xffffffffu, tppp, off);
            n1pp  += __shfl_xor_sync(0xffffffffu, n1pp, off);
            cvcfp += __shfl_xor_sync(0xffffffffu, cvcfp, off);
            cf2p  += __shfl_xor_sync(0xffffffffu, cf2p, off);
        }
        tpp = tppp; n1 = sqrtf(n1pp); cvcf = cvcfp; cf2 = cf2p;
    }

    const int* adjp = adj + ((size_t)b * TOT + cidx) * K;
    float best = -3.4e38f; int ksel = 0;

    if (FIRST) {
        #pragma unroll
        for (int k = 0; k < K; k++) {
            int idx = __ldg(&adjp[k]);
            float2 ssq = __ldg(&ssqb[idx]);
            float lg = (ssq.x + tpp - mean_a) * inv_a + beta_a;
            if (lg > best) { best = lg; ksel = k; }
        }
    } else {
        #pragma unroll
        for (int h = 0; h < 2; h++) {
            int idxs[10]; float cvp[10], cfp[10];
            #pragma unroll
            for (int j = 0; j < 10; j++) {
                int idx = __ldg(&adjp[h * 10 + j]);
                idxs[j] = idx;
                const float4* pv = (const float4*)(xTb + (size_t)idx * C);
                float4 pA = __ldg(&pv[sub]);
                float4 pB = __ldg(&pv[8 + sub]);
                cvp[j] = dot8(cvA, cvB, pA, pB);
                cfp[j] = dot8(cfA, cfB, pA, pB);
            }
            #pragma unroll
            for (int off = 1; off <= 4; off <<= 1) {
                #pragma unroll
                for (int j = 0; j < 10; j++) {
                    cvp[j] += __shfl_xor_sync(0xffffffffu, cvp[j], off);
                    cfp[j] += __shfl_xor_sync(0xffffffffu, cfp[j], off);
                }
            }
            #pragma unroll
            for (int j = 0; j < 10; j++) {
                float2 ssq = __ldg(&ssqb[idxs[j]]);
                float lg = (ssq.x + tpp - mean_a) * inv_a + beta_a;
                float ccv = cvp[j] - cvcf;
                float nn  = ssq.y - 2.f * cfp[j] + cf2;
                float cosv = ccv / fmaxf(n1 * sqrtf(nn), 1e-8f);
                lg *= fminf(fmaxf(1.f + cosv, 0.f), 1.f);
                if (lg > best) { best = lg; ksel = h * 10 + j; }
            }
        }
    }

    int nidx = __ldg(&adjp[ksel]);
    {
        const float4* pv = (const float4*)(xTb + (size_t)nidx * C);
        cfA = __ldg(&pv[sub]); cfB = __ldg(&pv[8 + sub]);
    }

    // coalesced curve store + persist state
    {
        float4* cvo = (float4*)(g_curves + ((size_t)step * NW + w) * C);
        cvo[sub] = cfA; cvo[8 + sub] = cfB;
        float4* cfo = (float4*)(g_curf + (size_t)w * C);
        cfo[sub] = cfA; cfo[8 + sub] = cfB;
        float4* pfo = (float4*)(g_pref + (size_t)w * C);
        pfo[sub] = pfA; pfo[8 + sub] = pfB;
        if (sub == 0) g_curidx[w] = nidx;
    }

    if (step < STEPS - 1) {
        const float4* mv = (const float4*)mom_w;   // 2 rows x 32 float4
        float l0 = dot8(cfA, cfB, __ldg(&mv[sub]),      __ldg(&mv[8 + sub]))
                 + dot8(pfA, pfB, __ldg(&mv[16 + sub]), __ldg(&mv[24 + sub]));
        float l1 = dot8(cfA, cfB, __ldg(&mv[32 + sub]), __ldg(&mv[40 + sub]))
                 + dot8(pfA, pfB, __ldg(&mv[48 + sub]), __ldg(&mv[56 + sub]));
        #pragma unroll
        for (int off = 1; off <= 4; off <<= 1) {
            l0 += __shfl_xor_sync(0xffffffffu, l0, off);
            l1 += __shfl_xor_sync(0xffffffffu, l1, off);
        }
        if (sub == 0) {
            float inv0 = __ldg(&mom_gamma[0]) / sqrtf(__ldg(&mom_var[0]) + BN_EPS);
            float inv1 = __ldg(&mom_gamma[1]) / sqrtf(__ldg(&mom_var[1]) + BN_EPS);
            float m0 = (l0 - __ldg(&mom_mean[0])) * inv0 + __ldg(&mom_beta[0]);
            float m1 = (l1 - __ldg(&mom_mean[1])) * inv1 + __ldg(&mom_beta[1]);
            float mx = fmaxf(m0, m1);
            float e0 = expf(m0 - mx), e1 = expf(m1 - mx);
            float s = e0 + e1;
            g_S[b * 1024 + n]       = e0 / s;
            g_S[b * 1024 + 512 + n] = e1 / s;
        }
    }
}

// ---------------- reorder: g_curves[step][w][ch] -> out[b][ch][n][step] ----------------
__global__ __launch_bounds__(256)
void reorder_kernel(float* __restrict__ out) {
    __shared__ float tile[16][8 * C + 1];
    int b = blockIdx.x >> 5;
    int n0 = (blockIdx.x & 31) * 16;
    int t = threadIdx.x;

    #pragma unroll
    for (int step = 0; step < STEPS; step++) {
        #pragma unroll
        for (int i4 = 0; i4 < 4; i4++) {
            int i = i4 * 4 + (t >> 6);
            int ch = t & 63;
            int w = b * CN + n0 + i;
            tile[i][step * 64 + ch] =
                g_curves[((size_t)step * NW + w) * C + ch];
        }
    }
    __syncthreads();

    int i = t & 15, ch0 = t >> 4;
    #pragma unroll
    for (int cc = 0; cc < 4; cc++) {
        int ch = ch0 + cc * 16;
        float v[8];
        #pragma unroll
        for (int s = 0; s < STEPS; s++) v[s] = tile[i][s * 64 + ch];
        float4* dst = (float4*)(out +
            ((((size_t)b * C + ch) * CN) + n0 + i) * STEPS);
        dst[0] = make_float4(v[0], v[1], v[2], v[3]);
        dst[1] = make_float4(v[4], v[5], v[6], v[7]);
    }
}

extern "C" void kernel_launch(void* const* d_in, const int* in_sizes, int n_in,
                              void* d_out, int out_size) {
    const float* x          = (const float*)d_in[1];
    const int*   adj        = (const int*)  d_in[2];
    const int*   cur        = (const int*)  d_in[3];
    const float* agent_w    = (const float*)d_in[4];
    const float* agent_gamma= (const float*)d_in[5];
    const float* agent_beta = (const float*)d_in[6];
    const float* agent_mean = (const float*)d_in[7];
    const float* agent_var  = (const float*)d_in[8];
    const float* mom_w      = (const float*)d_in[9];
    const float* mom_gamma  = (const float*)d_in[10];
    const float* mom_beta   = (const float*)d_in[11];
    const float* mom_mean   = (const float*)d_in[12];
    const float* mom_var    = (const float*)d_in[13];
    float* out = (float*)d_out;

    dim3 tb(8, 32), tg(TOT / 32, C / 32, BN);
    transpose_x_kernel<<<tg, tb>>>(x);
    ssq_kernel<<<BN * TOT / 256, 256>>>(agent_w);

    int blocks = (NW * 8) / 256;
    walk_step_kernel<true><<<blocks, 256>>>(adj, cur, agent_w, agent_gamma,
        agent_beta, agent_mean, agent_var, mom_w, mom_gamma, mom_beta,
        mom_mean, mom_var, 0);
    for (int s = 1; s < STEPS; s++) {
        walk_step_kernel<false><<<blocks, 256>>>(adj, cur, agent_w, agent_gamma,
            agent_beta, agent_mean, agent_var, mom_w, mom_gamma, mom_beta,
            mom_mean, mom_var, s);
    }
    reorder_kernel<<<BN * (CN / 16), 256>>>(out);
}

// round 4
// speedup vs baseline: 1.1309x; 1.1309x over previous
#include <cuda_runtime.h>

#define TOT 8192
#define BN 16
#define C 64
#define K 20
#define CN 512
#define NW (BN*CN)
#define STEPS 8
#define BN_EPS 1e-5f

// ---- device scratch (static; no allocations) ----
__device__ float g_xT[(size_t)BN*TOT*C];        // x transposed (b,node,ch) 32MB
__device__ float g_s[(size_t)BN*TOT];           // per-node dot(x, w_lo)
__device__ float g_curves[(size_t)STEPS*NW*C];  // [step][w][ch] 16MB
__device__ float g_curf[(size_t)NW*C];
__device__ float g_pref[(size_t)NW*C];
__device__ int   g_curidx[NW];
__device__ float g_S[BN*2*CN];                  // softmax exchange

// ---------------- transpose x (b,c,tot) -> xT (b,tot,c) ----------------
__global__ __launch_bounds__(256)
void transpose_x_kernel(const float* __restrict__ x) {
    __shared__ float tile[32][33];
    int b = blockIdx.z;
    int node0 = blockIdx.x * 32;
    int ch0 = blockIdx.y * 32;
    int tx = threadIdx.x;   // 0..7
    int ty = threadIdx.y;   // 0..31
    const float4* src = (const float4*)(x + (size_t)b * C * TOT
                                          + (size_t)(ch0 + ty) * TOT + node0);
    float4 v = __ldg(&src[tx]);
    tile[ty][tx*4+0] = v.x; tile[ty][tx*4+1] = v.y;
    tile[ty][tx*4+2] = v.z; tile[ty][tx*4+3] = v.w;
    __syncthreads();
    int r = ty, c4 = tx * 4;
    float4 o = make_float4(tile[c4][r], tile[c4+1][r], tile[c4+2][r], tile[c4+3][r]);
    float4* dst = (float4*)(g_xT + (size_t)b * TOT * C + (size_t)(node0 + r) * C + ch0);
    dst[tx] = o;
}

// ---------------- per-node s = dot(x, w_lo) ----------------
__global__ __launch_bounds__(256)
void s_kernel(const float* __restrict__ agent_w) {
    int t = blockIdx.x * 256 + threadIdx.x;
    const float4* row = (const float4*)(g_xT + (size_t)t * C);
    const float4* wv = (const float4*)agent_w;
    float s = 0.f;
    #pragma unroll
    for (int i = 0; i < 16; i++) {
        float4 v = row[i];
        float4 wl = __ldg(&wv[i]);
        s += v.x*wl.x + v.y*wl.y + v.z*wl.z + v.w*wl.w;
    }
    g_s[t] = s;
}

__device__ __forceinline__ float dot8(const float4& a0, const float4& a1,
                                      const float4& b0, const float4& b1) {
    return a0.x*b0.x + a0.y*b0.y + a0.z*b0.z + a0.w*b0.w
         + a1.x*b1.x + a1.y*b1.y + a1.z*b1.z + a1.w*b1.w;
}

// ---------------- one walk step ----------------
// 16 lanes per walker (2 walkers/warp). Within a walker: two 8-lane groups,
// group `half` handles neighbors [10*half, 10*half+10); each group is
// channel-split 8-wide (lane sub owns channels 4sub..4sub+3 and 32+4sub..).
template<bool FIRST>
__global__ __launch_bounds__(256, 3)
void walk_step_kernel(
    const int* __restrict__ adj, const int* __restrict__ cur0,
    const float* __restrict__ agent_w,
    const float* __restrict__ agent_gamma, const float* __restrict__ agent_beta,
    const float* __restrict__ agent_mean,  const float* __restrict__ agent_var,
    const float* __restrict__ mom_w,
    const float* __restrict__ mom_gamma, const float* __restrict__ mom_beta,
    const float* __restrict__ mom_mean,  const float* __restrict__ mom_var,
    int step)
{
    int lane = threadIdx.x & 31;
    int sub = lane & 7;
    int half = (lane >> 3) & 1;
    int w = blockIdx.x * 16 + ((threadIdx.x >> 5) << 1) + (lane >> 4);
    int b = w >> 9;
    int n = w & 511;

    const float4* wv = (const float4*)agent_w;
    float4 whA = __ldg(&wv[16 + sub]), whB = __ldg(&wv[24 + sub]);  // agent_w[64:128]

    float inv_a  = __ldg(agent_gamma) / sqrtf(__ldg(agent_var) + BN_EPS);
    float mean_a = __ldg(agent_mean);
    float beta_a = __ldg(agent_beta);

    const float* xTb = g_xT + (size_t)b * TOT * C;
    const float* sb  = g_s + (size_t)b * TOT;

    float4 cfA, cfB, pfA, pfB, cvA, cvB;
    int cidx;
    float tpp, n1 = 0.f;

    if (FIRST) {
        cidx = __ldg(&cur0[w]);
        const float4* pv = (const float4*)(xTb + (size_t)cidx * C);
        pfA = __ldg(&pv[sub]); pfB = __ldg(&pv[8 + sub]);
        tpp = dot8(pfA, pfB, whA, whB);
        #pragma unroll
        for (int off = 1; off <= 4; off <<= 1)
            tpp += __shfl_xor_sync(0xffffffffu, tpp, off);
        cfA = make_float4(0.f,0.f,0.f,0.f); cfB = cfA; cvA = cfA; cvB = cfA;
    } else {
        cidx = g_curidx[w];
        const float4* cf = (const float4*)(g_curf + (size_t)w * C);
        cfA = cf[sub]; cfB = cf[8 + sub];
        const float4* pf = (const float4*)(g_pref + (size_t)w * C);
        pfA = pf[sub]; pfB = pf[8 + sub];
        float a0 = g_S[b * 1024 + 2 * n];
        float a1 = g_S[b * 1024 + 2 * n + 1];
        pfA.x = cfA.x*a0 + pfA.x*a1;  pfA.y = cfA.y*a0 + pfA.y*a1;
        pfA.z = cfA.z*a0 + pfA.z*a1;  pfA.w = cfA.w*a0 + pfA.w*a1;
        pfB.x = cfB.x*a0 + pfB.x*a1;  pfB.y = cfB.y*a0 + pfB.y*a1;
        pfB.z = cfB.z*a0 + pfB.z*a1;  pfB.w = cfB.w*a0 + pfB.w*a1;
        cvA.x = cfA.x - pfA.x; cvA.y = cfA.y - pfA.y;
        cvA.z = cfA.z - pfA.z; cvA.w = cfA.w - pfA.w;
        cvB.x = cfB.x - pfB.x; cvB.y = cfB.y - pfB.y;
        cvB.z = cfB.z - pfB.z; cvB.w = cfB.w - pfB.w;

        float tppp = dot8(pfA, pfB, whA, whB);
        float n1pp = dot8(cvA, cvB, cvA, cvB);
        #pragma unroll
        for (int off = 1; off <= 4; off <<= 1) {
            tppp += __shfl_xor_sync(0xffffffffu, tppp, off);
            n1pp += __shfl_xor_sync(0xffffffffu, n1pp, off);
        }
        tpp = tppp; n1 = sqrtf(n1pp);
    }

    const int* adjp = adj + ((size_t)b * TOT + cidx) * K;

    // ---- batched loads for this group's 10 neighbors (full MLP) ----
    float sv[10], cc[10], nn[10];
    #pragma unroll
    for (int j = 0; j < 10; j++) {
        int idx = __ldg(&adjp[half * 10 + j]);
        sv[j] = __ldg(&sb[idx]);
        if (!FIRST) {
            const float4* pv = (const float4*)(xTb + (size_t)idx * C);
            float4 pA = __ldg(&pv[sub]);
            float4 pB = __ldg(&pv[8 + sub]);
            float d0 = pA.x - cfA.x, d1 = pA.y - cfA.y;
            float d2 = pA.z - cfA.z, d3 = pA.w - cfA.w;
            float d4 = pB.x - cfB.x, d5 = pB.y - cfB.y;
            float d6 = pB.z - cfB.z, d7 = pB.w - cfB.w;
            cc[j] = cvA.x*d0 + cvA.y*d1 + cvA.z*d2 + cvA.w*d3
                  + cvB.x*d4 + cvB.y*d5 + cvB.z*d6 + cvB.w*d7;
            nn[j] = d0*d0 + d1*d1 + d2*d2 + d3*d3 + d4*d4 + d5*d5 + d6*d6 + d7*d7;
        }
    }

    if (!FIRST) {
        #pragma unroll
        for (int off = 1; off <= 4; off <<= 1) {
            #pragma unroll
            for (int j = 0; j < 10; j++) {
                cc[j] += __shfl_xor_sync(0xffffffffu, cc[j], off);
                nn[j] += __shfl_xor_sync(0xffffffffu, nn[j], off);
            }
        }
    }

    // ---- group-local logits + argmax ----
    float best = -3.4e38f; int ksel = 0;
    #pragma unroll
    for (int j = 0; j < 10; j++) {
        float lg = (sv[j] + tpp - mean_a) * inv_a + beta_a;
        if (!FIRST) {
            float cosv = cc[j] / fmaxf(n1 * sqrtf(nn[j]), 1e-8f);
            lg *= fminf(fmaxf(1.f + cosv, 0.f), 1.f);
        }
        if (lg > best) { best = lg; ksel = half * 10 + j; }
    }

    // ---- cross-half combine (first-max tie break: half 0 wins ties) ----
    float obest = __shfl_xor_sync(0xffffffffu, best, 8);
    int   oksel = __shfl_xor_sync(0xffffffffu, ksel, 8);
    float lgA = half ? obest : best;   int kA = half ? oksel : ksel;
    float lgB = half ? best  : obest;  int kB = half ? ksel  : oksel;
    int kwin = (lgB > lgA) ? kB : kA;

    int nidx = __ldg(&adjp[kwin]);
    {
        const float4* pv = (const float4*)(xTb + (size_t)nidx * C);
        cfA = __ldg(&pv[sub]); cfB = __ldg(&pv[8 + sub]);
    }

    // ---- coalesced curve store + persist state (halves split the row) ----
    {
        float4* cvo = (float4*)(g_curves + ((size_t)step * NW + w) * C);
        float4* cfo = (float4*)(g_curf + (size_t)w * C);
        float4* pfo = (float4*)(g_pref + (size_t)w * C);
        if (half == 0) {
            cvo[sub] = cfA; cfo[sub] = cfA; pfo[sub] = pfA;
        } else {
            cvo[8 + sub] = cfB; cfo[8 + sub] = cfB; pfo[8 + sub] = pfB;
        }
        if ((lane & 15) == 0) g_curidx[w] = nidx;
    }

    if (step < STEPS - 1) {
        const float4* mv = (const float4*)mom_w;   // 2 rows x 32 float4
        float l0 = dot8(cfA, cfB, __ldg(&mv[sub]),      __ldg(&mv[8 + sub]))
                 + dot8(pfA, pfB, __ldg(&mv[16 + sub]), __ldg(&mv[24 + sub]));
        float l1 = dot8(cfA, cfB, __ldg(&mv[32 + sub]), __ldg(&mv[40 + sub]))
                 + dot8(pfA, pfB, __ldg(&mv[48 + sub]), __ldg(&mv[56 + sub]));
        #pragma unroll
        for (int off = 1; off <= 4; off <<= 1) {
            l0 += __shfl_xor_sync(0xffffffffu, l0, off);
            l1 += __shfl_xor_sync(0xffffffffu, l1, off);
        }
        if ((lane & 15) == 0) {
            float inv0 = __ldg(&mom_gamma[0]) / sqrtf(__ldg(&mom_var[0]) + BN_EPS);
            float inv1 = __ldg(&mom_gamma[1]) / sqrtf(__ldg(&mom_var[1]) + BN_EPS);
            float m0 = (l0 - __ldg(&mom_mean[0])) * inv0 + __ldg(&mom_beta[0]);
            float m1 = (l1 - __ldg(&mom_mean[1])) * inv1 + __ldg(&mom_beta[1]);
            float mx = fmaxf(m0, m1);
            float e0 = expf(m0 - mx), e1 = expf(m1 - mx);
            float s = e0 + e1;
            g_S[b * 1024 + n]       = e0 / s;
            g_S[b * 1024 + 512 + n] = e1 / s;
        }
    }
}

// ---------------- reorder: g_curves[step][w][ch] -> out[b][ch][n][step] ----------------
__global__ __launch_bounds__(256)
void reorder_kernel(float* __restrict__ out) {
    __shared__ float tile[16][8 * C + 1];
    int b = blockIdx.x >> 5;
    int n0 = (blockIdx.x & 31) * 16;
    int t = threadIdx.x;

    #pragma unroll
    for (int step = 0; step < STEPS; step++) {
        #pragma unroll
        for (int i4 = 0; i4 < 4; i4++) {
            int i = i4 * 4 + (t >> 6);
            int ch = t & 63;
            int w = b * CN + n0 + i;
            tile[i][step * 64 + ch] =
                g_curves[((size_t)step * NW + w) * C + ch];
        }
    }
    __syncthreads();

    int i = t & 15, ch0 = t >> 4;
    #pragma unroll
    for (int cc = 0; cc < 4; cc++) {
        int ch = ch0 + cc * 16;
        float v[8];
        #pragma unroll
        for (int s = 0; s < STEPS; s++) v[s] = tile[i][s * 64 + ch];
        float4* dst = (float4*)(out +
            ((((size_t)b * C + ch) * CN) + n0 + i) * STEPS);
        dst[0] = make_float4(v[0], v[1], v[2], v[3]);
        dst[1] = make_float4(v[4], v[5], v[6], v[7]);
    }
}

extern "C" void kernel_launch(void* const* d_in, const int* in_sizes, int n_in,
                              void* d_out, int out_size) {
    const float* x          = (const float*)d_in[1];
    const int*   adj        = (const int*)  d_in[2];
    const int*   cur        = (const int*)  d_in[3];
    const float* agent_w    = (const float*)d_in[4];
    const float* agent_gamma= (const float*)d_in[5];
    const float* agent_beta = (const float*)d_in[6];
    const float* agent_mean = (const float*)d_in[7];
    const float* agent_var  = (const float*)d_in[8];
    const float* mom_w      = (const float*)d_in[9];
    const float* mom_gamma  = (const float*)d_in[10];
    const float* mom_beta   = (const float*)d_in[11];
    const float* mom_mean   = (const float*)d_in[12];
    const float* mom_var    = (const float*)d_in[13];
    float* out = (float*)d_out;

    dim3 tb(8, 32), tg(TOT / 32, C / 32, BN);
    transpose_x_kernel<<<tg, tb>>>(x);
    s_kernel<<<BN * TOT / 256, 256>>>(agent_w);

    int blocks = NW / 16;   // 512 blocks of 256 threads (16 walkers/block)
    walk_step_kernel<true><<<blocks, 256>>>(adj, cur, agent_w, agent_gamma,
        agent_beta, agent_mean, agent_var, mom_w, mom_gamma, mom_beta,
        mom_mean, mom_var, 0);
    for (int s = 1; s < STEPS; s++) {
        walk_step_kernel<false><<<blocks, 256>>>(adj, cur, agent_w, agent_gamma,
            agent_beta, agent_mean, agent_var, mom_w, mom_gamma, mom_beta,
            mom_mean, mom_var, s);
    }
    reorder_kernel<<<BN * (CN / 16), 256>>>(out);
}

// round 5
// speedup vs baseline: 1.5267x; 1.3500x over previous
#include <cuda_runtime.h>
#include <cfloat>

#define TOT 8192
#define BN 16
#define C 64
#define K 20
#define CN 512
#define NW (BN*CN)
#define STEPS 8
#define BN_EPS 1e-5f

// ---- device scratch (static; no allocations) ----
__device__ float  g_xT[(size_t)BN*TOT*C];        // x transposed (b,node,ch) 32MB
__device__ float2 g_ssq[(size_t)BN*TOT];         // per-node (dot(x,w_lo), |x|^2)
__device__ float  g_curves[(size_t)STEPS*NW*C];  // [step][w][ch] 16MB
__device__ float  g_curf[(size_t)NW*C];
__device__ float  g_pref[(size_t)NW*C];
__device__ int    g_curidx[NW];
__device__ float  g_S[BN*2*CN];                  // softmax exchange

__device__ __forceinline__ float dot4(const float4& a, const float4& b) {
    return a.x*b.x + a.y*b.y + a.z*b.z + a.w*b.w;
}
__device__ __forceinline__ float dot8(const float4& a0, const float4& a1,
                                      const float4& b0, const float4& b1) {
    return dot4(a0,b0) + dot4(a1,b1);
}

// ---------------- fused: transpose x -> xT, and per-node (s, |x|^2) ----------------
// block: 256 threads, covers 32 nodes x 64 channels for one batch b.
__global__ __launch_bounds__(256)
void prep_kernel(const float* __restrict__ x, const float* __restrict__ agent_w) {
    __shared__ float tile[64][33];
    int b = blockIdx.y;
    int node0 = blockIdx.x * 32;
    int t = threadIdx.x;
    int ty = t >> 3;      // channel 0..31 (and +32)
    int tx = t & 7;       // float4 index along nodes

    const float* xb = x + (size_t)b * C * TOT;
    float4 v0 = __ldg((const float4*)(xb + (size_t)ty * TOT + node0) + tx);
    float4 v1 = __ldg((const float4*)(xb + (size_t)(ty + 32) * TOT + node0) + tx);
    tile[ty][tx*4+0] = v0.x; tile[ty][tx*4+1] = v0.y;
    tile[ty][tx*4+2] = v0.z; tile[ty][tx*4+3] = v0.w;
    tile[ty+32][tx*4+0] = v1.x; tile[ty+32][tx*4+1] = v1.y;
    tile[ty+32][tx*4+2] = v1.z; tile[ty+32][tx*4+3] = v1.w;
    __syncthreads();

    int node = t >> 3;    // 0..31
    int j = t & 7;        // float4 index along channels
    float4 a = make_float4(tile[4*j+0][node], tile[4*j+1][node],
                           tile[4*j+2][node], tile[4*j+3][node]);
    float4 c = make_float4(tile[32+4*j+0][node], tile[32+4*j+1][node],
                           tile[32+4*j+2][node], tile[32+4*j+3][node]);
    float4* dst = (float4*)(g_xT + ((size_t)b * TOT + node0 + node) * C);
    dst[j] = a; dst[8 + j] = c;

    const float4* wv = (const float4*)agent_w;
    float4 wA = __ldg(&wv[j]), wB = __ldg(&wv[8 + j]);
    float s = dot4(a, wA) + dot4(c, wB);
    float q = dot4(a, a) + dot4(c, c);
    #pragma unroll
    for (int off = 1; off <= 4; off <<= 1) {
        s += __shfl_xor_sync(0xffffffffu, s, off);
        q += __shfl_xor_sync(0xffffffffu, q, off);
    }
    if (j == 0) g_ssq[(size_t)b * TOT + node0 + node] = make_float2(s, q);
}

// ---------------- one walk step; 8 lanes per walker, 8 walkers/block ----------------
template<bool FIRST>
__global__ __launch_bounds__(64, 8)
void walk_step_kernel(
    const int* __restrict__ adj, const int* __restrict__ cur0,
    const float* __restrict__ agent_w,
    const float* __restrict__ agent_gamma, const float* __restrict__ agent_beta,
    const float* __restrict__ agent_mean,  const float* __restrict__ agent_var,
    const float* __restrict__ mom_w,
    const float* __restrict__ mom_gamma, const float* __restrict__ mom_beta,
    const float* __restrict__ mom_mean,  const float* __restrict__ mom_var,
    int step)
{
    int sub = threadIdx.x & 7;
    int w = blockIdx.x * 8 + (threadIdx.x >> 3);
    int b = w >> 9;
    int n = w & 511;

    const float4* wv = (const float4*)agent_w;
    float4 whA = __ldg(&wv[16 + sub]), whB = __ldg(&wv[24 + sub]);  // agent_w[64:128]

    float inv_a  = __ldg(agent_gamma) / sqrtf(__ldg(agent_var) + BN_EPS);
    float mean_a = __ldg(agent_mean);
    float beta_a = __ldg(agent_beta);

    const float* xTb = g_xT + (size_t)b * TOT * C;
    const float2* ssqb = g_ssq + (size_t)b * TOT;

    float4 cfA, cfB, pfA, pfB, cvA, cvB;
    int cidx;
    float tpp, n1 = 0.f, cvcf = 0.f, cf2 = 0.f;

    if (FIRST) {
        cidx = __ldg(&cur0[w]);
        const float4* pv = (const float4*)(xTb + (size_t)cidx * C);
        pfA = __ldg(&pv[sub]); pfB = __ldg(&pv[8 + sub]);
        tpp = dot8(pfA, pfB, whA, whB);
        #pragma unroll
        for (int off = 1; off <= 4; off <<= 1)
            tpp += __shfl_xor_sync(0xffffffffu, tpp, off);
        cfA = make_float4(0.f,0.f,0.f,0.f); cfB = cfA; cvA = cfA; cvB = cfA;
    } else {
        cidx = g_curidx[w];
        const float4* cf = (const float4*)(g_curf + (size_t)w * C);
        cfA = cf[sub]; cfB = cf[8 + sub];
        const float4* pf = (const float4*)(g_pref + (size_t)w * C);
        pfA = pf[sub]; pfB = pf[8 + sub];
        float2 aa = ((const float2*)g_S)[b * 512 + n];   // entries 2n, 2n+1
        float a0 = aa.x, a1 = aa.y;
        pfA.x = cfA.x*a0 + pfA.x*a1;  pfA.y = cfA.y*a0 + pfA.y*a1;
        pfA.z = cfA.z*a0 + pfA.z*a1;  pfA.w = cfA.w*a0 + pfA.w*a1;
        pfB.x = cfB.x*a0 + pfB.x*a1;  pfB.y = cfB.y*a0 + pfB.y*a1;
        pfB.z = cfB.z*a0 + pfB.z*a1;  pfB.w = cfB.w*a0 + pfB.w*a1;
        cvA.x = cfA.x - pfA.x; cvA.y = cfA.y - pfA.y;
        cvA.z = cfA.z - pfA.z; cvA.w = cfA.w - pfA.w;
        cvB.x = cfB.x - pfB.x; cvB.y = cfB.y - pfB.y;
        cvB.z = cfB.z - pfB.z; cvB.w = cfB.w - pfB.w;

        float tppp  = dot8(pfA, pfB, whA, whB);
        float n1pp  = dot8(cvA, cvB, cvA, cvB);
        float cvcfp = dot8(cvA, cvB, cfA, cfB);
        float cf2p  = dot8(cfA, cfB, cfA, cfB);
        #pragma unroll
        for (int off = 1; off <= 4; off <<= 1) {
            tppp  += __shfl_xor_sync(0xffffffffu, tppp, off);
            n1pp  += __shfl_xor_sync(0xffffffffu, n1pp, off);
            cvcfp += __shfl_xor_sync(0xffffffffu, cvcfp, off);
            cf2p  += __shfl_xor_sync(0xffffffffu, cf2p, off);
        }
        tpp = tppp; n1 = sqrtf(n1pp); cvcf = cvcfp; cf2 = cf2p;
    }

    // ---- adjacency: 5 x int4 (80B, 16B-aligned) ----
    const int* adjp = adj + ((size_t)b * TOT + cidx) * K;
    const int4* adj4 = (const int4*)adjp;
    int idx[20];
    #pragma unroll
    for (int q = 0; q < 5; q++) {
        int4 t4 = __ldg(&adj4[q]);
        idx[4*q+0] = t4.x; idx[4*q+1] = t4.y; idx[4*q+2] = t4.z; idx[4*q+3] = t4.w;
    }

    float cvp[20], cfp[20];
    if (!FIRST) {
        #pragma unroll
        for (int k = 0; k < 20; k++) {
            const float4* pv = (const float4*)(xTb + (size_t)idx[k] * C);
            float4 pA = __ldg(&pv[sub]);
            float4 pB = __ldg(&pv[8 + sub]);
            cvp[k] = dot8(cvA, cvB, pA, pB);
            cfp[k] = dot8(cfA, cfB, pA, pB);
        }
        #pragma unroll
        for (int off = 1; off <= 4; off <<= 1) {
            #pragma unroll
            for (int k = 0; k < 20; k++) {
                cvp[k] += __shfl_xor_sync(0xffffffffu, cvp[k], off);
                cfp[k] += __shfl_xor_sync(0xffffffffu, cfp[k], off);
            }
        }
    }

    // ---- epilogue distributed: lane sub owns k = sub, sub+8, sub+16 ----
    float best = -FLT_MAX; int ksel = 0x7fffffff;
    #pragma unroll
    for (int t = 0; t < 3; t++) {
        int k = sub + 8 * t;
        if (k < 20) {
            float2 ssq = __ldg(&ssqb[idx[k]]);
            float lg = (ssq.x + tpp - mean_a) * inv_a + beta_a;
            if (!FIRST) {
                float cc = cvp[k] - cvcf;
                float nn = ssq.y - 2.f * cfp[k] + cf2;
                float cosv = cc / fmaxf(n1 * sqrtf(nn), 1e-8f);
                lg *= fminf(fmaxf(1.f + cosv, 0.f), 1.f);
            }
            if (lg > best) { best = lg; ksel = k; }
        }
    }
    // cross-lane argmax, ties -> smallest k (first-max semantics)
    #pragma unroll
    for (int off = 1; off <= 4; off <<= 1) {
        float ob = __shfl_xor_sync(0xffffffffu, best, off);
        int   ok = __shfl_xor_sync(0xffffffffu, ksel, off);
        if (ob > best || (ob == best && ok < ksel)) { best = ob; ksel = ok; }
    }

    int nidx = __ldg(&adjp[ksel]);
    {
        const float4* pv = (const float4*)(xTb + (size_t)nidx * C);
        cfA = __ldg(&pv[sub]); cfB = __ldg(&pv[8 + sub]);
    }

    // ---- coalesced curve store + persist state ----
    {
        float4* cvo = (float4*)(g_curves + ((size_t)step * NW + w) * C);
        cvo[sub] = cfA; cvo[8 + sub] = cfB;
        float4* cfo = (float4*)(g_curf + (size_t)w * C);
        cfo[sub] = cfA; cfo[8 + sub] = cfB;
        float4* pfo = (float4*)(g_pref + (size_t)w * C);
        pfo[sub] = pfA; pfo[8 + sub] = pfB;
        if (sub == 0) g_curidx[w] = nidx;
    }

    if (step < STEPS - 1) {
        const float4* mv = (const float4*)mom_w;   // 2 rows x 32 float4
        float l0 = dot8(cfA, cfB, __ldg(&mv[sub]),      __ldg(&mv[8 + sub]))
                 + dot8(pfA, pfB, __ldg(&mv[16 + sub]), __ldg(&mv[24 + sub]));
        float l1 = dot8(cfA, cfB, __ldg(&mv[32 + sub]), __ldg(&mv[40 + sub]))
                 + dot8(pfA, pfB, __ldg(&mv[48 + sub]), __ldg(&mv[56 + sub]));
        #pragma unroll
        for (int off = 1; off <= 4; off <<= 1) {
            l0 += __shfl_xor_sync(0xffffffffu, l0, off);
            l1 += __shfl_xor_sync(0xffffffffu, l1, off);
        }
        if (sub == 0) {
            float inv0 = __ldg(&mom_gamma[0]) / sqrtf(__ldg(&mom_var[0]) + BN_EPS);
            float inv1 = __ldg(&mom_gamma[1]) / sqrtf(__ldg(&mom_var[1]) + BN_EPS);
            float m0 = (l0 - __ldg(&mom_mean[0])) * inv0 + __ldg(&mom_beta[0]);
            float m1 = (l1 - __ldg(&mom_mean[1])) * inv1 + __ldg(&mom_beta[1]);
            float mx = fmaxf(m0, m1);
            float e0 = expf(m0 - mx), e1 = expf(m1 - mx);
            float s = e0 + e1;
            g_S[b * 1024 + n]       = e0 / s;
            g_S[b * 1024 + 512 + n] = e1 / s;
        }
    }
}

// ---------------- reorder: g_curves[step][w][ch] -> out[b][ch][n][step] ----------------
__global__ __launch_bounds__(256)
void reorder_kernel(float* __restrict__ out) {
    __shared__ float tile[16][8 * C + 1];
    int b = blockIdx.x >> 5;
    int n0 = (blockIdx.x & 31) * 16;
    int t = threadIdx.x;

    #pragma unroll
    for (int step = 0; step < STEPS; step++) {
        #pragma unroll
        for (int i4 = 0; i4 < 4; i4++) {
            int i = i4 * 4 + (t >> 6);
            int ch = t & 63;
            int w = b * CN + n0 + i;
            tile[i][step * 64 + ch] =
                g_curves[((size_t)step * NW + w) * C + ch];
        }
    }
    __syncthreads();

    int i = t & 15, ch0 = t >> 4;
    #pragma unroll
    for (int cc = 0; cc < 4; cc++) {
        int ch = ch0 + cc * 16;
        float v[8];
        #pragma unroll
        for (int s = 0; s < STEPS; s++) v[s] = tile[i][s * 64 + ch];
        float4* dst = (float4*)(out +
            ((((size_t)b * C + ch) * CN) + n0 + i) * STEPS);
        dst[0] = make_float4(v[0], v[1], v[2], v[3]);
        dst[1] = make_float4(v[4], v[5], v[6], v[7]);
    }
}

extern "C" void kernel_launch(void* const* d_in, const int* in_sizes, int n_in,
                              void* d_out, int out_size) {
    const float* x          = (const float*)d_in[1];
    const int*   adj        = (const int*)  d_in[2];
    const int*   cur        = (const int*)  d_in[3];
    const float* agent_w    = (const float*)d_in[4];
    const float* agent_gamma= (const float*)d_in[5];
    const float* agent_beta = (const float*)d_in[6];
    const float* agent_mean = (const float*)d_in[7];
    const float* agent_var  = (const float*)d_in[8];
    const float* mom_w      = (const float*)d_in[9];
    const float* mom_gamma  = (const float*)d_in[10];
    const float* mom_beta   = (const float*)d_in[11];
    const float* mom_mean   = (const float*)d_in[12];
    const float* mom_var    = (const float*)d_in[13];
    float* out = (float*)d_out;

    dim3 pg(TOT / 32, BN);
    prep_kernel<<<pg, 256>>>(x, agent_w);

    int blocks = NW / 8;   // 1024 blocks of 64 threads
    walk_step_kernel<true><<<blocks, 64>>>(adj, cur, agent_w, agent_gamma,
        agent_beta, agent_mean, agent_var, mom_w, mom_gamma, mom_beta,
        mom_mean, mom_var, 0);
    for (int s = 1; s < STEPS; s++) {
        walk_step_kernel<false><<<blocks, 64>>>(adj, cur, agent_w, agent_gamma,
            agent_beta, agent_mean, agent_var, mom_w, mom_gamma, mom_beta,
            mom_mean, mom_var, s);
    }
    reorder_kernel<<<BN * (CN / 16), 256>>>(out);
}